// round 14
// baseline (speedup 1.0000x reference)
#include <cuda_runtime.h>
#include <math.h>

#define B_ 16
#define N_ 64
#define E_ 512
#define C_ 512
#define H1_ 256
#define H2_ 128
#define H3_ 64
#define U_ 8
#define R_ 8
#define EH_ 64
#define EPS_ 1e-5f
#define NODE_OUT (B_*N_*N_*U_)

typedef unsigned long long ull;

__device__ __align__(16) float g_nodec[B_*N_*U_];
__device__ __align__(16) float g_rel[B_*N_*N_*R_];
__device__ int g_see[B_*N_*N_];
__device__ int g_cnt[B_*N_];

__device__ __forceinline__ void fma2(ull& d, ull a, ull b) {
    asm("fma.rn.f32x2 %0, %1, %2, %0;" : "+l"(d) : "l"(a), "l"(b));
}
__device__ __forceinline__ ull dup2(float x) {
    ull r; asm("mov.b64 %0, {%1, %1};" : "=l"(r) : "f"(x)); return r;
}
__device__ __forceinline__ void unpack2(ull p, float& lo, float& hi) {
    asm("mov.b64 {%0, %1}, %2;" : "=f"(lo), "=f"(hi) : "l"(p));
}
__device__ __forceinline__ void cpa16(float* s, const float* g) {
    unsigned ss = (unsigned)__cvta_generic_to_shared(s);
    asm volatile("cp.async.cg.shared.global [%0], [%1], 16;" :: "r"(ss), "l"(g) : "memory");
}
__device__ __forceinline__ void cp_commit() {
    asm volatile("cp.async.commit_group;" ::: "memory");
}
template<int W> __device__ __forceinline__ void cp_wait() {
    asm volatile("cp.async.wait_group %0;" :: "n"(W) : "memory");
}
__device__ __forceinline__ void bulk_s2g(void* g, unsigned s, unsigned bytes) {
    asm volatile("cp.async.bulk.global.shared::cta.bulk_group [%0], [%1], %2;"
        :: "l"(g), "r"(s), "r"(bytes) : "memory");
}
__device__ __forceinline__ void bulk_commit() {
    asm volatile("cp.async.bulk.commit_group;" ::: "memory");
}
template<int W> __device__ __forceinline__ void bulk_wait() {
    asm volatile("cp.async.bulk.wait_group %0;" :: "n"(W) : "memory");
}
__device__ __forceinline__ float sigf(float x) { return 1.0f / (1.0f + __expf(-x)); }

// ===========================================================================
// Role: zero-fill 16 output rows via TMA bulk stores; 2 rows per warp-leader.
// ===========================================================================
__device__ void zf_role(float* sm, int z, float* __restrict__ out) {
    int tid = threadIdx.x;
    float4* zb = (float4*)sm;
    const float4 zv = make_float4(0.f, 0.f, 0.f, 0.f);
    #pragma unroll
    for (int q = 0; q < 8; q++) zb[tid + 256*q] = zv;   // 32KB zeros
    asm volatile("fence.proxy.async.shared::cta;" ::: "memory");
    __syncthreads();
    if ((tid & 15) == 0) {
        int r = tid >> 4;                 // half-warp leader = row 0..15
        int bi = z*16 + r;
        unsigned s = (unsigned)__cvta_generic_to_shared(sm);
        bulk_s2g(out + (size_t)bi * 512, s, 2048);          // node row
        float* oE = out + (size_t)NODE_OUT + (size_t)bi * 32768;
        #pragma unroll
        for (int c = 0; c < 4; c++)
            bulk_s2g(oE + c*8192, s, 32768);                // edge row
        bulk_commit();
        bulk_wait<0>();
        asm volatile("fence.proxy.async;" ::: "memory");
    }
}

// ===========================================================================
// Role: edge MLP, 2 rows per block; column-split warp tiling in e2.
// ===========================================================================
__device__ void edge_role(float* sm, int bi0,
    const float* __restrict__ bbox, const float* __restrict__ dir,
    const float* __restrict__ prio,
    const float* __restrict__ we1, const float* __restrict__ be1,
    const float* __restrict__ we2, const float* __restrict__ be2,
    const float* __restrict__ wei, const float* __restrict__ bei)
{
    float* sE    = sm;           // 4352 (64x68)
    float* sW2   = sm + 4352;    // 4096
    float* sWei  = sm + 8448;    // 512
    float* sWe1  = sm + 8960;    // 1152
    float* sAttr = sm + 10112;   // 576
    float* sP    = sm + 10688;   // 64
    float* sBe2  = sm + 10752;   // 64
    float* sBei  = sm + 10816;   // 8
    int tid = threadIdx.x;
    int b = bi0 >> 6;

    for (int l = tid; l < 576; l += 256) {
        int r = l / 9, c = l - r*9;
        float v;
        if (c < 4)      v = bbox[(b*N_ + r)*4 + c] * (1.0f/1024.0f);
        else if (c < 8) v = dir[(b*N_ + r)*4 + c - 4];
        else            v = prio[b*N_ + r];
        sAttr[l] = v;
    }
    for (int l = tid; l < 1152; l += 256) sWe1[l] = we1[l];
    for (int l = tid; l < 1024; l += 256) ((float4*)sW2)[l] = ((const float4*)we2)[l];
    for (int l = tid; l < 512; l += 256) sWei[l] = wei[l];
    if (tid < 64) sBe2[tid] = be2[tid];
    if (tid < 8)  sBei[tid] = bei[tid];
    __syncthreads();

    // Column-split tiling: warp w -> rows [(w>>1)*16, +16), cols [(w&1)*32, +32)
    int w = tid >> 5, lane = tid & 31;
    int rbase = (w >> 1) * 16 + (lane >> 3) * 4;   // 4 rows per thread
    int cbase = (w & 1) * 32 + (lane & 7) * 4;     // 4 cols per thread

    for (int ii = 0; ii < 2; ii++) {
        int bi = bi0 + ii;
        int i = bi & 63;

        if (tid < 64) {
            float p = be1[tid];
            #pragma unroll
            for (int c = 0; c < 9; c++) p = fmaf(sAttr[i*9 + c], sWe1[c*64 + tid], p);
            sP[tid] = p;
        }
        __syncthreads();

        {   // e1[j][h] = relu(P[h] + attr_j @ we1[9:])
            int j = tid >> 2, hq = tid & 3;
            float a[9];
            #pragma unroll
            for (int c = 0; c < 9; c++) a[c] = sAttr[j*9 + c];
            #pragma unroll
            for (int h0 = hq*16; h0 < hq*16 + 16; h0 += 4) {
                float4 o; float* op = &o.x;
                #pragma unroll
                for (int t = 0; t < 4; t++) {
                    int h = h0 + t;
                    float q = 0.0f;
                    #pragma unroll
                    for (int c = 0; c < 9; c++) q = fmaf(a[c], sWe1[(9+c)*64 + h], q);
                    op[t] = fmaxf(sP[h] + q, 0.0f);
                }
                *(float4*)&sE[j*68 + h0] = o;
            }
        }
        __syncthreads();

        // e2 = relu(e1 @ we2 + be2): 64x64 K=64, f32x2, col-split warps
        {
            ull acc[4][2] = {};
            #pragma unroll
            for (int h0 = 0; h0 < 64; h0 += 4) {
                float4 a0 = *(const float4*)&sE[(rbase+0)*68 + h0];
                float4 a1 = *(const float4*)&sE[(rbase+1)*68 + h0];
                float4 a2 = *(const float4*)&sE[(rbase+2)*68 + h0];
                float4 a3 = *(const float4*)&sE[(rbase+3)*68 + h0];
                const float* p0 = &a0.x;
                const float* p1 = &a1.x;
                const float* p2 = &a2.x;
                const float* p3 = &a3.x;
                #pragma unroll
                for (int t = 0; t < 4; t++) {
                    ulonglong2 ww = *(const ulonglong2*)&sW2[(h0+t)*64 + cbase];
                    ull d0 = dup2(p0[t]);
                    ull d1 = dup2(p1[t]);
                    ull d2 = dup2(p2[t]);
                    ull d3 = dup2(p3[t]);
                    fma2(acc[0][0], d0, ww.x); fma2(acc[0][1], d0, ww.y);
                    fma2(acc[1][0], d1, ww.x); fma2(acc[1][1], d1, ww.y);
                    fma2(acc[2][0], d2, ww.x); fma2(acc[2][1], d2, ww.y);
                    fma2(acc[3][0], d3, ww.x); fma2(acc[3][1], d3, ww.y);
                }
            }
            __syncthreads();
            #pragma unroll
            for (int rr = 0; rr < 4; rr++) {
                float v[4];
                unpack2(acc[rr][0], v[0], v[1]);
                unpack2(acc[rr][1], v[2], v[3]);
                float4 o;
                o.x = fmaxf(v[0] + sBe2[cbase+0], 0.0f);
                o.y = fmaxf(v[1] + sBe2[cbase+1], 0.0f);
                o.z = fmaxf(v[2] + sBe2[cbase+2], 0.0f);
                o.w = fmaxf(v[3] + sBe2[cbase+3], 0.0f);
                *(float4*)&sE[(rbase+rr)*68 + cbase] = o;
            }
        }
        __syncthreads();

        if (tid < 128) {  // rel = sigmoid(e2 @ wei + bei), float4 e-loads
            int j = tid >> 1, rh = tid & 1;
            float a0 = sBei[rh*4+0], a1 = sBei[rh*4+1], a2 = sBei[rh*4+2], a3 = sBei[rh*4+3];
            #pragma unroll
            for (int o0 = 0; o0 < 64; o0 += 4) {
                float4 e4 = *(const float4*)&sE[j*68 + o0];
                const float* pe = &e4.x;
                #pragma unroll
                for (int t = 0; t < 4; t++) {
                    float4 wv = *(const float4*)&sWei[(o0+t)*8 + rh*4];
                    a0 = fmaf(pe[t], wv.x, a0); a1 = fmaf(pe[t], wv.y, a1);
                    a2 = fmaf(pe[t], wv.z, a2); a3 = fmaf(pe[t], wv.w, a3);
                }
            }
            float4 o;
            o.x = sigf(a0); o.y = sigf(a1); o.z = sigf(a2); o.w = sigf(a3);
            *(float4*)&g_rel[(bi*64 + j)*8 + rh*4] = o;
        }
        __syncthreads();
    }
}

// ===========================================================================
// Role: node MLP, 8 rows/block (2KB-float DB weight chunks)
// ===========================================================================
__device__ void node_role(float* sm, int blk, const float* __restrict__ roi,
    const float* __restrict__ w1, const float* __restrict__ b1,
    const float* __restrict__ g1, const float* __restrict__ bt1,
    const float* __restrict__ m1, const float* __restrict__ v1,
    const float* __restrict__ w2, const float* __restrict__ b2,
    const float* __restrict__ g2, const float* __restrict__ bt2,
    const float* __restrict__ m2, const float* __restrict__ v2,
    const float* __restrict__ w3, const float* __restrict__ b3,
    const float* __restrict__ wn, const float* __restrict__ bnc)
{
    float* sX  = sm;            // 4096
    float* sX1 = sm + 4096;     // 2048
    float* sX2 = sm + 6144;     // 1024
    float* sX3 = sm + 7168;     // 512
    float* sWn = sm + 7680;     // 512
    float* sWa = sm + 8192;     // 2048
    float* sWb = sm + 10240;    // 2048
    int tid = threadIdx.x;
    int m0 = blk * 8;

    {
        const float4* xs = (const float4*)(roi + (size_t)m0 * C_);
        float4* xd = (float4*)sX;
        #pragma unroll
        for (int q = 0; q < 4; q++) xd[tid + 256*q] = xs[tid + 256*q];
        if (tid < 128) ((float4*)sWn)[tid] = __ldg((const float4*)wn + tid);
    }
    #pragma unroll
    for (int j = 0; j < 2; j++) { int l = tid + 256*j; cpa16(&sWa[l*4], w1 + l*4); }
    cp_commit();
    __syncthreads();

    // ---- layer 1: 8x256, K=512 ----
    {
        int c = tid & 63, rp = tid >> 6;
        ull acc[2][2] = {};
        for (int ch = 0; ch < 64; ch++) {
            float* wb = (ch & 1) ? sWb : sWa;
            if (ch < 63) {
                const float* src = w1 + (ch+1) * 2048;
                float* dst = (ch & 1) ? sWa : sWb;
                #pragma unroll
                for (int j = 0; j < 2; j++) { int l = tid + 256*j; cpa16(&dst[l*4], src + l*4); }
            }
            cp_commit(); cp_wait<1>();
            __syncthreads();
            int k0 = ch * 8;
            #pragma unroll
            for (int k = 0; k < 8; k++) {
                ulonglong2 w = *(const ulonglong2*)&wb[k*256 + c*4];
                ull d0 = dup2(sX[(rp*2+0)*512 + k0 + k]);
                ull d1 = dup2(sX[(rp*2+1)*512 + k0 + k]);
                fma2(acc[0][0], d0, w.x); fma2(acc[0][1], d0, w.y);
                fma2(acc[1][0], d1, w.x); fma2(acc[1][1], d1, w.y);
            }
            __syncthreads();
        }
        float bb[4], sc[4], mm[4], be[4];
        #pragma unroll
        for (int j = 0; j < 4; j++) {
            int n = c*4 + j;
            bb[j] = b1[n]; sc[j] = g1[n] * rsqrtf(v1[n] + EPS_);
            mm[j] = m1[n]; be[j] = bt1[n];
        }
        #pragma unroll
        for (int rr = 0; rr < 2; rr++) {
            float v[4];
            unpack2(acc[rr][0], v[0], v[1]);
            unpack2(acc[rr][1], v[2], v[3]);
            float4 o;
            o.x = fmaxf((v[0] + bb[0] - mm[0]) * sc[0] + be[0], 0.0f);
            o.y = fmaxf((v[1] + bb[1] - mm[1]) * sc[1] + be[1], 0.0f);
            o.z = fmaxf((v[2] + bb[2] - mm[2]) * sc[2] + be[2], 0.0f);
            o.w = fmaxf((v[3] + bb[3] - mm[3]) * sc[3] + be[3], 0.0f);
            *(float4*)&sX1[(rp*2+rr)*256 + c*4] = o;
        }
    }
    __syncthreads();

    // ---- layer 2: 8x128, K=256 ----
    {
        #pragma unroll
        for (int j = 0; j < 2; j++) { int l = tid + 256*j; cpa16(&sWa[l*4], w2 + l*4); }
        cp_commit();
        int c = tid & 31, rp = tid >> 5;
        ull acc[2] = {};
        for (int ch = 0; ch < 16; ch++) {
            float* wb = (ch & 1) ? sWb : sWa;
            if (ch < 15) {
                const float* src = w2 + (ch+1) * 2048;
                float* dst = (ch & 1) ? sWa : sWb;
                #pragma unroll
                for (int j = 0; j < 2; j++) { int l = tid + 256*j; cpa16(&dst[l*4], src + l*4); }
            }
            cp_commit(); cp_wait<1>();
            __syncthreads();
            int k0 = ch * 16;
            #pragma unroll
            for (int k = 0; k < 16; k++) {
                ulonglong2 w = *(const ulonglong2*)&wb[k*128 + c*4];
                ull d0 = dup2(sX1[rp*256 + k0 + k]);
                fma2(acc[0], d0, w.x); fma2(acc[1], d0, w.y);
            }
            __syncthreads();
        }
        float v[4];
        unpack2(acc[0], v[0], v[1]);
        unpack2(acc[1], v[2], v[3]);
        float4 o; float* op = &o.x;
        #pragma unroll
        for (int j = 0; j < 4; j++) {
            int n = c*4 + j;
            float scv = g2[n] * rsqrtf(v2[n] + EPS_);
            op[j] = fmaxf((v[j] + b2[n] - m2[n]) * scv + bt2[n], 0.0f);
        }
        *(float4*)&sX2[rp*128 + c*4] = o;
    }
    __syncthreads();

    // ---- layer 3: 8x64, K=128 ----
    {
        #pragma unroll
        for (int j = 0; j < 2; j++) { int l = tid + 256*j; cpa16(&sWa[l*4], w3 + l*4); }
        cp_commit();
        int c = tid & 15, rp = tid >> 4;
        ull acc[2] = {};
        for (int ch = 0; ch < 4; ch++) {
            float* wb = (ch & 1) ? sWb : sWa;
            if (ch < 3) {
                const float* src = w3 + (ch+1) * 2048;
                float* dst = (ch & 1) ? sWa : sWb;
                #pragma unroll
                for (int j = 0; j < 2; j++) { int l = tid + 256*j; cpa16(&dst[l*4], src + l*4); }
            }
            cp_commit(); cp_wait<1>();
            __syncthreads();
            if (tid < 128) {
                int k0 = ch * 32;
                #pragma unroll 8
                for (int k = 0; k < 32; k++) {
                    ulonglong2 w = *(const ulonglong2*)&wb[k*64 + c*4];
                    ull d0 = dup2(sX2[rp*128 + k0 + k]);
                    fma2(acc[0], d0, w.x); fma2(acc[1], d0, w.y);
                }
            }
            __syncthreads();
        }
        if (tid < 128) {
            float v[4];
            unpack2(acc[0], v[0], v[1]);
            unpack2(acc[1], v[2], v[3]);
            float4 o;
            o.x = fmaxf(v[0] + b3[c*4+0], 0.0f);
            o.y = fmaxf(v[1] + b3[c*4+1], 0.0f);
            o.z = fmaxf(v[2] + b3[c*4+2], 0.0f);
            o.w = fmaxf(v[3] + b3[c*4+3], 0.0f);
            *(float4*)&sX3[rp*64 + c*4] = o;
        }
    }
    __syncthreads();

    if (tid < 64) {
        int r = tid >> 3, u = tid & 7;
        float s = bnc[u];
        #pragma unroll 8
        for (int k = 0; k < H3_; k++) s = fmaf(sX3[r*64 + k], sWn[k*8 + u], s);
        g_nodec[(m0 + r)*U_ + u] = sigf(s);
    }
}

// ===========================================================================
// Role: see-table build (segmented count + prefix, exact sequential order)
// ===========================================================================
__device__ void see_role(int* ism, int b, const int* __restrict__ ei) {
    int* ssrc = ism;
    int* sdst = ism + 512;
    int* scnt = ism + 1024;
    int tid = threadIdx.x;
    for (int l = tid; l < E_; l += 256) {
        ssrc[l] = ei[b*2*E_ + l];
        sdst[l] = ei[b*2*E_ + E_ + l];
    }
    __syncthreads();
    int s = tid >> 6;
    int n = tid & 63;
    int* row = g_see + (b*N_ + n) * N_;
    #pragma unroll
    for (int q = 0; q < 16; q++) row[s*16 + q] = 0;
    int c = 0;
    #pragma unroll 8
    for (int e = s*128; e < s*128 + 128; e++) if (sdst[e] == n) c++;
    scnt[tid] = c;
    __syncthreads();
    int base = 0;
    #pragma unroll
    for (int t = 0; t < 4; t++) if (t < s) base += scnt[t*64 + n];
    int p = base + 1;
    #pragma unroll 8
    for (int e = s*128; e < s*128 + 128; e++) {
        if (sdst[e] == n) { if (p < N_) row[p] = ssrc[e]; p++; }
    }
    if (s == 0) row[0] = n;
    if (s == 3) g_cnt[b*N_ + n] = min(base + c + 1, N_);
}

// ===========================================================================
// Mega kernel: [0,128) node, [128,192) zf(16 rows), [192,208) see,
//              [208,720) edge (2 rows each)
// ===========================================================================
__global__ void __launch_bounds__(256)
mega_kernel(const float* __restrict__ roi,
    const float* __restrict__ bbox, const float* __restrict__ dir,
    const float* __restrict__ prio,
    const float* __restrict__ w1, const float* __restrict__ b1,
    const float* __restrict__ g1, const float* __restrict__ bt1,
    const float* __restrict__ m1, const float* __restrict__ v1,
    const float* __restrict__ w2, const float* __restrict__ b2,
    const float* __restrict__ g2, const float* __restrict__ bt2,
    const float* __restrict__ m2, const float* __restrict__ v2,
    const float* __restrict__ w3, const float* __restrict__ b3,
    const float* __restrict__ wn, const float* __restrict__ bnc,
    const float* __restrict__ we1, const float* __restrict__ be1,
    const float* __restrict__ we2, const float* __restrict__ be2,
    const float* __restrict__ wei, const float* __restrict__ bei,
    const int* __restrict__ eidx, float* __restrict__ out)
{
    extern __shared__ __align__(16) float smx[];
    int blk = blockIdx.x;
    if (blk < 128) {
        node_role(smx, blk, roi, w1, b1, g1, bt1, m1, v1,
                  w2, b2, g2, bt2, m2, v2, w3, b3, wn, bnc);
    } else if (blk < 192) {
        zf_role(smx, blk - 128, out);
    } else if (blk < 208) {
        see_role((int*)smx, blk - 192, eidx);
    } else {
        edge_role(smx, (blk - 208) * 2, bbox, dir, prio, we1, be1, we2, be2, wei, bei);
    }
}

// ===========================================================================
// Scatter: write only nonzero entries (j<cnt, k<cnt) from rel/nodec.
// ===========================================================================
__global__ void __launch_bounds__(128)
scatter_kernel(float* __restrict__ out) {
    __shared__ int ss[64];
    __shared__ int scnt;
    int tid = threadIdx.x, bi = blockIdx.x;
    int b = bi >> 6;
    if (tid < 64) ss[tid] = g_see[bi*64 + tid];
    if (tid == 0) scnt = g_cnt[bi];
    __syncthreads();
    int cnt = scnt;

    float4* oN = (float4*)(out + (size_t)bi * 512);
    for (int l = tid; l < cnt*2; l += 128) {
        int j = l >> 1, h = l & 1;
        oN[l] = __ldg((const float4*)(g_nodec + (b*N_ + ss[j])*U_) + h);
    }

    const float4* relb = (const float4*)(g_rel + b * (N_*N_*R_));
    float4* oE = (float4*)(out + (size_t)NODE_OUT + (size_t)bi * 32768);
    int tot = cnt * cnt;
    for (int p = tid; p < tot; p += 128) {
        int j = p / cnt, k = p - j*cnt;
        const float4* rp = relb + (ss[j]*64 + ss[k]) * 2;
        float4 v0 = __ldg(rp), v1 = __ldg(rp + 1);
        oE[(j*64 + k)*2]     = v0;
        oE[(j*64 + k)*2 + 1] = v1;
    }
}

// ===========================================================================
extern "C" void kernel_launch(void* const* d_in, const int* in_sizes, int n_in,
                              void* d_out, int out_size) {
    const float* roi  = (const float*)d_in[0];
    const float* bbox = (const float*)d_in[1];
    const float* dir  = (const float*)d_in[2];
    const float* prio = (const float*)d_in[3];
    const float* w1   = (const float*)d_in[4];
    const float* b1   = (const float*)d_in[5];
    const float* g1   = (const float*)d_in[6];
    const float* bt1  = (const float*)d_in[7];
    const float* m1   = (const float*)d_in[8];
    const float* v1   = (const float*)d_in[9];
    const float* w2   = (const float*)d_in[10];
    const float* b2   = (const float*)d_in[11];
    const float* g2   = (const float*)d_in[12];
    const float* bt2  = (const float*)d_in[13];
    const float* m2   = (const float*)d_in[14];
    const float* v2   = (const float*)d_in[15];
    const float* w3   = (const float*)d_in[16];
    const float* b3   = (const float*)d_in[17];
    const float* wn   = (const float*)d_in[18];
    const float* bnc  = (const float*)d_in[19];
    const float* we1  = (const float*)d_in[20];
    const float* be1  = (const float*)d_in[21];
    const float* we2  = (const float*)d_in[22];
    const float* be2  = (const float*)d_in[23];
    const float* wei  = (const float*)d_in[24];
    const float* bei  = (const float*)d_in[25];
    const int*   eidx = (const int*)d_in[26];
    float* out = (float*)d_out;

    cudaFuncSetAttribute(mega_kernel,
        cudaFuncAttributeMaxDynamicSharedMemorySize, 49152);

    mega_kernel<<<720, 256, 49152>>>(roi, bbox, dir, prio,
        w1, b1, g1, bt1, m1, v1,
        w2, b2, g2, bt2, m2, v2,
        w3, b3, wn, bnc,
        we1, be1, we2, be2, wei, bei, eidx, out);
    scatter_kernel<<<1024, 128>>>(out);
}

// round 15
// speedup vs baseline: 1.1055x; 1.1055x over previous
#include <cuda_runtime.h>
#include <math.h>

#define B_ 16
#define N_ 64
#define E_ 512
#define C_ 512
#define H1_ 256
#define H2_ 128
#define H3_ 64
#define U_ 8
#define R_ 8
#define EH_ 64
#define EPS_ 1e-5f
#define NODE_OUT (B_*N_*N_*U_)

typedef unsigned long long ull;

__device__ __align__(16) float g_nodec[B_*N_*U_];
__device__ __align__(16) float g_rel[B_*N_*N_*R_];
__device__ int g_see[B_*N_*N_];
__device__ int g_cnt[B_*N_];

__device__ __forceinline__ void fma2(ull& d, ull a, ull b) {
    asm("fma.rn.f32x2 %0, %1, %2, %0;" : "+l"(d) : "l"(a), "l"(b));
}
__device__ __forceinline__ ull dup2(float x) {
    ull r; asm("mov.b64 %0, {%1, %1};" : "=l"(r) : "f"(x)); return r;
}
__device__ __forceinline__ void unpack2(ull p, float& lo, float& hi) {
    asm("mov.b64 {%0, %1}, %2;" : "=f"(lo), "=f"(hi) : "l"(p));
}
__device__ __forceinline__ void cpa16(float* s, const float* g) {
    unsigned ss = (unsigned)__cvta_generic_to_shared(s);
    asm volatile("cp.async.cg.shared.global [%0], [%1], 16;" :: "r"(ss), "l"(g) : "memory");
}
__device__ __forceinline__ void cp_commit() {
    asm volatile("cp.async.commit_group;" ::: "memory");
}
template<int W> __device__ __forceinline__ void cp_wait() {
    asm volatile("cp.async.wait_group %0;" :: "n"(W) : "memory");
}
__device__ __forceinline__ void bulk_s2g(void* g, unsigned s, unsigned bytes) {
    asm volatile("cp.async.bulk.global.shared::cta.bulk_group [%0], [%1], %2;"
        :: "l"(g), "r"(s), "r"(bytes) : "memory");
}
__device__ __forceinline__ void bulk_commit() {
    asm volatile("cp.async.bulk.commit_group;" ::: "memory");
}
template<int W> __device__ __forceinline__ void bulk_wait() {
    asm volatile("cp.async.bulk.wait_group %0;" :: "n"(W) : "memory");
}
__device__ __forceinline__ float sigf(float x) { return 1.0f / (1.0f + __expf(-x)); }

// ===========================================================================
// Role: zero-fill 8 output rows via TMA bulk stores; 1 row per warp-leader.
// ===========================================================================
__device__ void zf_role(float* sm, int z, float* __restrict__ out) {
    int tid = threadIdx.x;
    float4* zb = (float4*)sm;
    const float4 zv = make_float4(0.f, 0.f, 0.f, 0.f);
    #pragma unroll
    for (int q = 0; q < 8; q++) zb[tid + 256*q] = zv;   // 32KB zeros
    asm volatile("fence.proxy.async.shared::cta;" ::: "memory");
    __syncthreads();
    if ((tid & 31) == 0) {
        int r = tid >> 5;                 // warp id = row 0..7
        int bi = z*8 + r;
        unsigned s = (unsigned)__cvta_generic_to_shared(sm);
        bulk_s2g(out + (size_t)bi * 512, s, 2048);          // node row
        float* oE = out + (size_t)NODE_OUT + (size_t)bi * 32768;
        #pragma unroll
        for (int c = 0; c < 4; c++)
            bulk_s2g(oE + c*8192, s, 32768);                // edge row
        bulk_commit();
        bulk_wait<0>();
        asm volatile("fence.proxy.async;" ::: "memory");
    }
}

// ===========================================================================
// Role: edge MLP, 2 rows per block FUSED: single e2 pass shares W loads.
// smem: sE 2x(64x68)=8704 (overlays transient sWe1/sAttr after phase 1),
//       sW2 4096, sWei 512, sP 128, sBe2 64, sBei 8  -> 13512 floats (54KB)
// ===========================================================================
__device__ void edge_role(float* sm, int bi0,
    const float* __restrict__ bbox, const float* __restrict__ dir,
    const float* __restrict__ prio,
    const float* __restrict__ we1, const float* __restrict__ be1,
    const float* __restrict__ we2, const float* __restrict__ be2,
    const float* __restrict__ wei, const float* __restrict__ bei)
{
    float* sE    = sm;            // 8704 (row stride 4352)
    float* sWe1  = sm;            // transient [0,1152)
    float* sAttr = sm + 1152;     // transient [1152,1728)
    float* sW2   = sm + 8704;     // 4096
    float* sWei  = sm + 12800;    // 512
    float* sP    = sm + 13312;    // 128 (2 rows x 64)
    float* sBe2  = sm + 13440;    // 64
    float* sBei  = sm + 13504;    // 8
    int tid = threadIdx.x;
    int b = bi0 >> 6;

    for (int l = tid; l < 576; l += 256) {
        int r = l / 9, c = l - r*9;
        float v;
        if (c < 4)      v = bbox[(b*N_ + r)*4 + c] * (1.0f/1024.0f);
        else if (c < 8) v = dir[(b*N_ + r)*4 + c - 4];
        else            v = prio[b*N_ + r];
        sAttr[l] = v;
    }
    for (int l = tid; l < 1152; l += 256) sWe1[l] = we1[l];
    for (int l = tid; l < 1024; l += 256) ((float4*)sW2)[l] = ((const float4*)we2)[l];
    for (int l = tid; l < 512; l += 256) sWei[l] = wei[l];
    if (tid < 64) sBe2[tid] = be2[tid];
    if (tid < 8)  sBei[tid] = bei[tid];
    __syncthreads();

    // ---- phase 1: q (regs, once per block) + P (both rows) ----
    int jq = tid >> 2, hq = tid & 3;
    float q[16];
    {
        float a[9];
        #pragma unroll
        for (int c = 0; c < 9; c++) a[c] = sAttr[jq*9 + c];
        #pragma unroll
        for (int t = 0; t < 16; t++) {
            int h = hq*16 + t;
            float s = 0.0f;
            #pragma unroll
            for (int c = 0; c < 9; c++) s = fmaf(a[c], sWe1[(9+c)*64 + h], s);
            q[t] = s;
        }
    }
    float pv = 0.0f;
    if (tid < 128) {
        int row = tid >> 6, hh = tid & 63;
        int i = (bi0 + row) & 63;
        pv = be1[hh];
        #pragma unroll
        for (int c = 0; c < 9; c++) pv = fmaf(sAttr[i*9 + c], sWe1[c*64 + hh], pv);
    }
    __syncthreads();          // all reads of sWe1/sAttr complete
    if (tid < 128) sP[tid] = pv;
    __syncthreads();

    // ---- phase 2: e1 for both rows (overwrites transient region) ----
    #pragma unroll
    for (int row = 0; row < 2; row++) {
        #pragma unroll
        for (int t4 = 0; t4 < 4; t4++) {
            int h0 = hq*16 + t4*4;
            float4 o;
            o.x = fmaxf(sP[row*64 + h0+0] + q[t4*4+0], 0.0f);
            o.y = fmaxf(sP[row*64 + h0+1] + q[t4*4+1], 0.0f);
            o.z = fmaxf(sP[row*64 + h0+2] + q[t4*4+2], 0.0f);
            o.w = fmaxf(sP[row*64 + h0+3] + q[t4*4+3], 0.0f);
            *(float4*)&sE[row*4352 + jq*68 + h0] = o;
        }
    }
    __syncthreads();

    // ---- phase 3: e2 for BOTH rows, W loaded once per h-group ----
    int tc = tid & 15, tr = tid >> 4;
    {
        ull acc[2][4][2] = {};
        #pragma unroll
        for (int h0 = 0; h0 < 64; h0 += 4) {
            ulonglong2 w0 = *(const ulonglong2*)&sW2[(h0+0)*64 + tc*4];
            ulonglong2 w1 = *(const ulonglong2*)&sW2[(h0+1)*64 + tc*4];
            ulonglong2 w2 = *(const ulonglong2*)&sW2[(h0+2)*64 + tc*4];
            ulonglong2 w3 = *(const ulonglong2*)&sW2[(h0+3)*64 + tc*4];
            #pragma unroll
            for (int row = 0; row < 2; row++) {
                #pragma unroll
                for (int rr = 0; rr < 4; rr++) {
                    float4 a = *(const float4*)&sE[row*4352 + (tr*4+rr)*68 + h0];
                    ull d;
                    d = dup2(a.x); fma2(acc[row][rr][0], d, w0.x); fma2(acc[row][rr][1], d, w0.y);
                    d = dup2(a.y); fma2(acc[row][rr][0], d, w1.x); fma2(acc[row][rr][1], d, w1.y);
                    d = dup2(a.z); fma2(acc[row][rr][0], d, w2.x); fma2(acc[row][rr][1], d, w2.y);
                    d = dup2(a.w); fma2(acc[row][rr][0], d, w3.x); fma2(acc[row][rr][1], d, w3.y);
                }
            }
        }
        __syncthreads();   // all reads of e1 done before overwrite
        #pragma unroll
        for (int row = 0; row < 2; row++) {
            #pragma unroll
            for (int rr = 0; rr < 4; rr++) {
                float v[4];
                unpack2(acc[row][rr][0], v[0], v[1]);
                unpack2(acc[row][rr][1], v[2], v[3]);
                float4 o;
                o.x = fmaxf(v[0] + sBe2[tc*4+0], 0.0f);
                o.y = fmaxf(v[1] + sBe2[tc*4+1], 0.0f);
                o.z = fmaxf(v[2] + sBe2[tc*4+2], 0.0f);
                o.w = fmaxf(v[3] + sBe2[tc*4+3], 0.0f);
                *(float4*)&sE[row*4352 + (tr*4+rr)*68 + tc*4] = o;
            }
        }
    }
    __syncthreads();

    // ---- phase 4: rel for both rows, all 256 threads ----
    {
        int row = tid >> 7, jr = tid & 127;
        int j = jr >> 1, rh = jr & 1;
        float a0 = sBei[rh*4+0], a1 = sBei[rh*4+1], a2 = sBei[rh*4+2], a3 = sBei[rh*4+3];
        #pragma unroll
        for (int o0 = 0; o0 < 64; o0 += 4) {
            float4 e4 = *(const float4*)&sE[row*4352 + j*68 + o0];
            const float* pe = &e4.x;
            #pragma unroll
            for (int t = 0; t < 4; t++) {
                float4 wv = *(const float4*)&sWei[(o0+t)*8 + rh*4];
                a0 = fmaf(pe[t], wv.x, a0); a1 = fmaf(pe[t], wv.y, a1);
                a2 = fmaf(pe[t], wv.z, a2); a3 = fmaf(pe[t], wv.w, a3);
            }
        }
        float4 o;
        o.x = sigf(a0); o.y = sigf(a1); o.z = sigf(a2); o.w = sigf(a3);
        *(float4*)&g_rel[((bi0 + row)*64 + j)*8 + rh*4] = o;
    }
}

// ===========================================================================
// Role: node MLP, 8 rows/block (2KB-float DB weight chunks)
// ===========================================================================
__device__ void node_role(float* sm, int blk, const float* __restrict__ roi,
    const float* __restrict__ w1, const float* __restrict__ b1,
    const float* __restrict__ g1, const float* __restrict__ bt1,
    const float* __restrict__ m1, const float* __restrict__ v1,
    const float* __restrict__ w2, const float* __restrict__ b2,
    const float* __restrict__ g2, const float* __restrict__ bt2,
    const float* __restrict__ m2, const float* __restrict__ v2,
    const float* __restrict__ w3, const float* __restrict__ b3,
    const float* __restrict__ wn, const float* __restrict__ bnc)
{
    float* sX  = sm;            // 4096
    float* sX1 = sm + 4096;     // 2048
    float* sX2 = sm + 6144;     // 1024
    float* sX3 = sm + 7168;     // 512
    float* sWn = sm + 7680;     // 512
    float* sWa = sm + 8192;     // 2048
    float* sWb = sm + 10240;    // 2048
    int tid = threadIdx.x;
    int m0 = blk * 8;

    {
        const float4* xs = (const float4*)(roi + (size_t)m0 * C_);
        float4* xd = (float4*)sX;
        #pragma unroll
        for (int q = 0; q < 4; q++) xd[tid + 256*q] = xs[tid + 256*q];
        if (tid < 128) ((float4*)sWn)[tid] = __ldg((const float4*)wn + tid);
    }
    #pragma unroll
    for (int j = 0; j < 2; j++) { int l = tid + 256*j; cpa16(&sWa[l*4], w1 + l*4); }
    cp_commit();
    __syncthreads();

    // ---- layer 1: 8x256, K=512 ----
    {
        int c = tid & 63, rp = tid >> 6;
        ull acc[2][2] = {};
        for (int ch = 0; ch < 64; ch++) {
            float* wb = (ch & 1) ? sWb : sWa;
            if (ch < 63) {
                const float* src = w1 + (ch+1) * 2048;
                float* dst = (ch & 1) ? sWa : sWb;
                #pragma unroll
                for (int j = 0; j < 2; j++) { int l = tid + 256*j; cpa16(&dst[l*4], src + l*4); }
            }
            cp_commit(); cp_wait<1>();
            __syncthreads();
            int k0 = ch * 8;
            #pragma unroll
            for (int k = 0; k < 8; k++) {
                ulonglong2 w = *(const ulonglong2*)&wb[k*256 + c*4];
                ull d0 = dup2(sX[(rp*2+0)*512 + k0 + k]);
                ull d1 = dup2(sX[(rp*2+1)*512 + k0 + k]);
                fma2(acc[0][0], d0, w.x); fma2(acc[0][1], d0, w.y);
                fma2(acc[1][0], d1, w.x); fma2(acc[1][1], d1, w.y);
            }
            __syncthreads();
        }
        float bb[4], sc[4], mm[4], be[4];
        #pragma unroll
        for (int j = 0; j < 4; j++) {
            int n = c*4 + j;
            bb[j] = b1[n]; sc[j] = g1[n] * rsqrtf(v1[n] + EPS_);
            mm[j] = m1[n]; be[j] = bt1[n];
        }
        #pragma unroll
        for (int rr = 0; rr < 2; rr++) {
            float v[4];
            unpack2(acc[rr][0], v[0], v[1]);
            unpack2(acc[rr][1], v[2], v[3]);
            float4 o;
            o.x = fmaxf((v[0] + bb[0] - mm[0]) * sc[0] + be[0], 0.0f);
            o.y = fmaxf((v[1] + bb[1] - mm[1]) * sc[1] + be[1], 0.0f);
            o.z = fmaxf((v[2] + bb[2] - mm[2]) * sc[2] + be[2], 0.0f);
            o.w = fmaxf((v[3] + bb[3] - mm[3]) * sc[3] + be[3], 0.0f);
            *(float4*)&sX1[(rp*2+rr)*256 + c*4] = o;
        }
    }
    __syncthreads();

    // ---- layer 2: 8x128, K=256 ----
    {
        #pragma unroll
        for (int j = 0; j < 2; j++) { int l = tid + 256*j; cpa16(&sWa[l*4], w2 + l*4); }
        cp_commit();
        int c = tid & 31, rp = tid >> 5;
        ull acc[2] = {};
        for (int ch = 0; ch < 16; ch++) {
            float* wb = (ch & 1) ? sWb : sWa;
            if (ch < 15) {
                const float* src = w2 + (ch+1) * 2048;
                float* dst = (ch & 1) ? sWa : sWb;
                #pragma unroll
                for (int j = 0; j < 2; j++) { int l = tid + 256*j; cpa16(&dst[l*4], src + l*4); }
            }
            cp_commit(); cp_wait<1>();
            __syncthreads();
            int k0 = ch * 16;
            #pragma unroll
            for (int k = 0; k < 16; k++) {
                ulonglong2 w = *(const ulonglong2*)&wb[k*128 + c*4];
                ull d0 = dup2(sX1[rp*256 + k0 + k]);
                fma2(acc[0], d0, w.x); fma2(acc[1], d0, w.y);
            }
            __syncthreads();
        }
        float v[4];
        unpack2(acc[0], v[0], v[1]);
        unpack2(acc[1], v[2], v[3]);
        float4 o; float* op = &o.x;
        #pragma unroll
        for (int j = 0; j < 4; j++) {
            int n = c*4 + j;
            float scv = g2[n] * rsqrtf(v2[n] + EPS_);
            op[j] = fmaxf((v[j] + b2[n] - m2[n]) * scv + bt2[n], 0.0f);
        }
        *(float4*)&sX2[rp*128 + c*4] = o;
    }
    __syncthreads();

    // ---- layer 3: 8x64, K=128 ----
    {
        #pragma unroll
        for (int j = 0; j < 2; j++) { int l = tid + 256*j; cpa16(&sWa[l*4], w3 + l*4); }
        cp_commit();
        int c = tid & 15, rp = tid >> 4;
        ull acc[2] = {};
        for (int ch = 0; ch < 4; ch++) {
            float* wb = (ch & 1) ? sWb : sWa;
            if (ch < 3) {
                const float* src = w3 + (ch+1) * 2048;
                float* dst = (ch & 1) ? sWa : sWb;
                #pragma unroll
                for (int j = 0; j < 2; j++) { int l = tid + 256*j; cpa16(&dst[l*4], src + l*4); }
            }
            cp_commit(); cp_wait<1>();
            __syncthreads();
            if (tid < 128) {
                int k0 = ch * 32;
                #pragma unroll 8
                for (int k = 0; k < 32; k++) {
                    ulonglong2 w = *(const ulonglong2*)&wb[k*64 + c*4];
                    ull d0 = dup2(sX2[rp*128 + k0 + k]);
                    fma2(acc[0], d0, w.x); fma2(acc[1], d0, w.y);
                }
            }
            __syncthreads();
        }
        if (tid < 128) {
            float v[4];
            unpack2(acc[0], v[0], v[1]);
            unpack2(acc[1], v[2], v[3]);
            float4 o;
            o.x = fmaxf(v[0] + b3[c*4+0], 0.0f);
            o.y = fmaxf(v[1] + b3[c*4+1], 0.0f);
            o.z = fmaxf(v[2] + b3[c*4+2], 0.0f);
            o.w = fmaxf(v[3] + b3[c*4+3], 0.0f);
            *(float4*)&sX3[rp*64 + c*4] = o;
        }
    }
    __syncthreads();

    if (tid < 64) {
        int r = tid >> 3, u = tid & 7;
        float s = bnc[u];
        #pragma unroll 8
        for (int k = 0; k < H3_; k++) s = fmaf(sX3[r*64 + k], sWn[k*8 + u], s);
        g_nodec[(m0 + r)*U_ + u] = sigf(s);
    }
}

// ===========================================================================
// Role: see-table build (segmented count + prefix, exact sequential order)
// ===========================================================================
__device__ void see_role(int* ism, int b, const int* __restrict__ ei) {
    int* ssrc = ism;
    int* sdst = ism + 512;
    int* scnt = ism + 1024;
    int tid = threadIdx.x;
    for (int l = tid; l < E_; l += 256) {
        ssrc[l] = ei[b*2*E_ + l];
        sdst[l] = ei[b*2*E_ + E_ + l];
    }
    __syncthreads();
    int s = tid >> 6;
    int n = tid & 63;
    int* row = g_see + (b*N_ + n) * N_;
    #pragma unroll
    for (int q = 0; q < 16; q++) row[s*16 + q] = 0;
    int c = 0;
    #pragma unroll 8
    for (int e = s*128; e < s*128 + 128; e++) if (sdst[e] == n) c++;
    scnt[tid] = c;
    __syncthreads();
    int base = 0;
    #pragma unroll
    for (int t = 0; t < 4; t++) if (t < s) base += scnt[t*64 + n];
    int p = base + 1;
    #pragma unroll 8
    for (int e = s*128; e < s*128 + 128; e++) {
        if (sdst[e] == n) { if (p < N_) row[p] = ssrc[e]; p++; }
    }
    if (s == 0) row[0] = n;
    if (s == 3) g_cnt[b*N_ + n] = min(base + c + 1, N_);
}

// ===========================================================================
// Mega kernel: [0,128) zf(TMA), [128,256) node, [256,272) see, [272,784) edge
// ===========================================================================
__global__ void __launch_bounds__(256)
mega_kernel(const float* __restrict__ roi,
    const float* __restrict__ bbox, const float* __restrict__ dir,
    const float* __restrict__ prio,
    const float* __restrict__ w1, const float* __restrict__ b1,
    const float* __restrict__ g1, const float* __restrict__ bt1,
    const float* __restrict__ m1, const float* __restrict__ v1,
    const float* __restrict__ w2, const float* __restrict__ b2,
    const float* __restrict__ g2, const float* __restrict__ bt2,
    const float* __restrict__ m2, const float* __restrict__ v2,
    const float* __restrict__ w3, const float* __restrict__ b3,
    const float* __restrict__ wn, const float* __restrict__ bnc,
    const float* __restrict__ we1, const float* __restrict__ be1,
    const float* __restrict__ we2, const float* __restrict__ be2,
    const float* __restrict__ wei, const float* __restrict__ bei,
    const int* __restrict__ eidx, float* __restrict__ out)
{
    extern __shared__ __align__(16) float smx[];
    int blk = blockIdx.x;
    if (blk < 128) {
        zf_role(smx, blk, out);
    } else if (blk < 256) {
        node_role(smx, blk - 128, roi, w1, b1, g1, bt1, m1, v1,
                  w2, b2, g2, bt2, m2, v2, w3, b3, wn, bnc);
    } else if (blk < 272) {
        see_role((int*)smx, blk - 256, eidx);
    } else {
        edge_role(smx, (blk - 272) * 2, bbox, dir, prio, we1, be1, we2, be2, wei, bei);
    }
}

// ===========================================================================
// Scatter: write only nonzero entries (j<cnt, k<cnt) from rel/nodec.
// ===========================================================================
__global__ void __launch_bounds__(128)
scatter_kernel(float* __restrict__ out) {
    __shared__ int ss[64];
    __shared__ int scnt;
    int tid = threadIdx.x, bi = blockIdx.x;
    int b = bi >> 6;
    if (tid < 64) ss[tid] = g_see[bi*64 + tid];
    if (tid == 0) scnt = g_cnt[bi];
    __syncthreads();
    int cnt = scnt;

    float4* oN = (float4*)(out + (size_t)bi * 512);
    for (int l = tid; l < cnt*2; l += 128) {
        int j = l >> 1, h = l & 1;
        oN[l] = __ldg((const float4*)(g_nodec + (b*N_ + ss[j])*U_) + h);
    }

    const float4* relb = (const float4*)(g_rel + b * (N_*N_*R_));
    float4* oE = (float4*)(out + (size_t)NODE_OUT + (size_t)bi * 32768);
    int tot = cnt * cnt;
    for (int p = tid; p < tot; p += 128) {
        int j = p / cnt, k = p - j*cnt;
        const float4* rp = relb + (ss[j]*64 + ss[k]) * 2;
        float4 v0 = __ldg(rp), v1 = __ldg(rp + 1);
        oE[(j*64 + k)*2]     = v0;
        oE[(j*64 + k)*2 + 1] = v1;
    }
}

// ===========================================================================
extern "C" void kernel_launch(void* const* d_in, const int* in_sizes, int n_in,
                              void* d_out, int out_size) {
    const float* roi  = (const float*)d_in[0];
    const float* bbox = (const float*)d_in[1];
    const float* dir  = (const float*)d_in[2];
    const float* prio = (const float*)d_in[3];
    const float* w1   = (const float*)d_in[4];
    const float* b1   = (const float*)d_in[5];
    const float* g1   = (const float*)d_in[6];
    const float* bt1  = (const float*)d_in[7];
    const float* m1   = (const float*)d_in[8];
    const float* v1   = (const float*)d_in[9];
    const float* w2   = (const float*)d_in[10];
    const float* b2   = (const float*)d_in[11];
    const float* g2   = (const float*)d_in[12];
    const float* bt2  = (const float*)d_in[13];
    const float* m2   = (const float*)d_in[14];
    const float* v2   = (const float*)d_in[15];
    const float* w3   = (const float*)d_in[16];
    const float* b3   = (const float*)d_in[17];
    const float* wn   = (const float*)d_in[18];
    const float* bnc  = (const float*)d_in[19];
    const float* we1  = (const float*)d_in[20];
    const float* be1  = (const float*)d_in[21];
    const float* we2  = (const float*)d_in[22];
    const float* be2  = (const float*)d_in[23];
    const float* wei  = (const float*)d_in[24];
    const float* bei  = (const float*)d_in[25];
    const int*   eidx = (const int*)d_in[26];
    float* out = (float*)d_out;

    cudaFuncSetAttribute(mega_kernel,
        cudaFuncAttributeMaxDynamicSharedMemorySize, 55296);

    mega_kernel<<<784, 256, 55296>>>(roi, bbox, dir, prio,
        w1, b1, g1, bt1, m1, v1,
        w2, b2, g2, bt2, m2, v2,
        w3, b3, wn, bnc,
        we1, be1, we2, be2, wei, bei, eidx, out);
    scatter_kernel<<<1024, 128>>>(out);
}